// round 5
// baseline (speedup 1.0000x reference)
#include <cuda_runtime.h>
#include <cuda_fp16.h>
#include <math.h>
#include <stdint.h>

#define T_TOK 8192
#define DIM   2048
#define NE    8
#define RK    16
#define ER    128

// ---------------- device scratch ----------------
__device__ int   g_idx[T_TOK];
__device__ float g_w[T_TOK];
__device__ __align__(256) __half g_xh[T_TOK * DIM];
__device__ __align__(256) __half g_wh[DIM * DIM];
__device__ __align__(256) __half g_lAt[ER * DIM];   // [n=e*16+r][k]
__device__ __align__(256) __half g_lBt[DIM * ER];   // [n][k2]
__device__ __align__(256) __half g_hm[T_TOK * ER];  // masked scaled h

__device__ __forceinline__ float gelu_exact(float v) {
    return 0.5f * v * (1.0f + erff(v * 0.7071067811865476f));
}
__device__ __forceinline__ uint32_t smem_u32(const void* p) {
    uint32_t a;
    asm("{ .reg .u64 t; cvta.to.shared.u64 t, %1; cvt.u32.u64 %0, t; }" : "=r"(a) : "l"(p));
    return a;
}
#define CP_ASYNC16(dst, src) asm volatile("cp.async.cg.shared.global [%0], [%1], 16;" :: "r"(dst), "l"(src))
#define CP_COMMIT()          asm volatile("cp.async.commit_group;" ::: "memory")
#define CP_WAIT(n)           asm volatile("cp.async.wait_group %0;" :: "n"(n) : "memory")

__device__ __forceinline__ void ldsm4(uint32_t* r, uint32_t addr) {
    asm volatile("ldmatrix.sync.aligned.m8n8.x4.shared.b16 {%0,%1,%2,%3}, [%4];"
        : "=r"(r[0]), "=r"(r[1]), "=r"(r[2]), "=r"(r[3]) : "r"(addr));
}
__device__ __forceinline__ void mma16816(float* d, const uint32_t* a, const uint32_t* b) {
    asm volatile("mma.sync.aligned.m16n8k16.row.col.f32.f16.f16.f32 "
        "{%0,%1,%2,%3}, {%4,%5,%6,%7}, {%8,%9}, {%0,%1,%2,%3};"
        : "+f"(d[0]), "+f"(d[1]), "+f"(d[2]), "+f"(d[3])
        : "r"(a[0]), "r"(a[1]), "r"(a[2]), "r"(a[3]), "r"(b[0]), "r"(b[1]));
}
// smem tile: rows x 64B (32 halves), swizzled
__device__ __forceinline__ uint32_t sw_off(int row, int chunk) {
    return (uint32_t)(row * 64 + ((chunk ^ ((row >> 1) & 3)) << 4));
}

// ---------------- fused x->fp16 convert + router ----------------
__global__ __launch_bounds__(256) void convx_router(
    const float* __restrict__ x, const float* __restrict__ gw,
    const float* __restrict__ gb, float* __restrict__ probs)
{
    extern __shared__ char smc[];
    float (*sgw)[DIM] = (float(*)[DIM])smc;
    const int warp = threadIdx.x >> 5, lane = threadIdx.x & 31;
    const int t = blockIdx.x * 8 + warp;
    const float* xr = x + (size_t)t * DIM;
    __half* xo = g_xh + (size_t)t * DIM;

    for (int i = threadIdx.x; i < NE * (DIM / 4); i += 256)
        ((float4*)smc)[i] = ((const float4*)gw)[i];
    __syncthreads();

    float acc[NE];
#pragma unroll
    for (int e = 0; e < NE; e++) acc[e] = 0.f;
#pragma unroll
    for (int i = 0; i < 16; i++) {
        int k = lane * 4 + i * 128;
        float4 v = *(const float4*)(xr + k);
        __half h[4] = {__float2half_rn(v.x), __float2half_rn(v.y),
                       __float2half_rn(v.z), __float2half_rn(v.w)};
        *(uint2*)(xo + k) = *(uint2*)h;
#pragma unroll
        for (int e = 0; e < NE; e++)
            acc[e] += v.x * sgw[e][k] + v.y * sgw[e][k + 1]
                    + v.z * sgw[e][k + 2] + v.w * sgw[e][k + 3];
    }
#pragma unroll
    for (int e = 0; e < NE; e++)
#pragma unroll
        for (int o = 16; o > 0; o >>= 1) acc[e] += __shfl_xor_sync(0xffffffffu, acc[e], o);
    if (lane == 0) {
        float m = -1e30f;
#pragma unroll
        for (int e = 0; e < NE; e++) { acc[e] += gb[e]; m = fmaxf(m, acc[e]); }
        float p[NE], s = 0.f;
#pragma unroll
        for (int e = 0; e < NE; e++) { p[e] = __expf(acc[e] - m); s += p[e]; }
        float inv = 1.f / s;
        int best = 0; float bp = -1.f;
#pragma unroll
        for (int e = 0; e < NE; e++) {
            p[e] *= inv;
            probs[t * NE + e] = p[e];
            if (p[e] > bp) { bp = p[e]; best = e; }
        }
        g_idx[t] = best; g_w[t] = bp;
    }
}

// ---------------- prep kernels ----------------
__global__ __launch_bounds__(256) void conv_w(const float* __restrict__ src, int n4) {
    int i = blockIdx.x * 256 + threadIdx.x;
    if (i >= n4) return;
    float4 v = ((const float4*)src)[i];
    __half h[4] = {__float2half_rn(v.x), __float2half_rn(v.y),
                   __float2half_rn(v.z), __float2half_rn(v.w)};
    ((uint2*)g_wh)[i] = *(uint2*)h;
}
__global__ __launch_bounds__(256) void pack_lA_kernel(const float* __restrict__ lA) {
    int idx = blockIdx.x * 256 + threadIdx.x;
    int k = idx & (DIM - 1), n = idx >> 11;
    g_lAt[idx] = __float2half_rn(lA[(size_t)((n >> 4) * DIM + k) * RK + (n & 15)]);
}
__global__ __launch_bounds__(256) void pack_lB_kernel(const float* __restrict__ lB) {
    int idx = blockIdx.x * 256 + threadIdx.x;
    int k2 = idx & 127, n = idx >> 7;
    g_lBt[idx] = __float2half_rn(lB[(size_t)((k2 >> 4) * RK + (k2 & 15)) * DIM + n]);
}

// ---------------- LoRA-A: g_hm = mask(w * gelu(xh @ lAt^T)) ----------------
#define LA_STAGE 16384
__global__ __launch_bounds__(256, 2) void loraA_mma() {
    extern __shared__ char sm[];
    uint32_t sb = smem_u32(sm);
    const int tid = threadIdx.x, wid = tid >> 5, lane = tid & 31;
    const int t0 = blockIdx.x * 128;
    const int warp_m = (wid & 3) * 32, warp_n = (wid >> 2) * 64;
    const int lrow = tid >> 2, lc = tid & 3;

    float acc[2][8][4];
#pragma unroll
    for (int a = 0; a < 2; a++)
#pragma unroll
        for (int b = 0; b < 8; b++)
#pragma unroll
            for (int c = 0; c < 4; c++) acc[a][b][c] = 0.f;

#define LA_ISSUE(s, k0) do {                                                  \
    uint32_t st = sb + (uint32_t)(s) * LA_STAGE;                              \
    _Pragma("unroll")                                                         \
    for (int i = 0; i < 2; i++) {                                             \
        int row = lrow + i * 64;                                              \
        CP_ASYNC16(st + sw_off(row, lc), g_xh + (size_t)(t0 + row) * DIM + (k0) + lc * 8); \
        CP_ASYNC16(st + 8192 + sw_off(row, lc), g_lAt + (size_t)row * DIM + (k0) + lc * 8); \
    }                                                                         \
    CP_COMMIT();                                                              \
} while (0)

    LA_ISSUE(0, 0);
    LA_ISSUE(1, 32);
    LA_ISSUE(2, 64);
    for (int c = 0; c < 64; c++) {
        if (c < 62) { CP_WAIT(2); } else if (c == 62) { CP_WAIT(1); } else { CP_WAIT(0); }
        __syncthreads();
        if (c + 3 < 64) LA_ISSUE((c + 3) & 3, (c + 3) * 32);
        uint32_t base = sb + (uint32_t)(c & 3) * LA_STAGE;
#pragma unroll
        for (int kk = 0; kk < 2; kk++) {
            uint32_t ah[2][4];
#pragma unroll
            for (int mi = 0; mi < 2; mi++) {
                int r = warp_m + mi * 16 + (lane & 15);
                ldsm4(ah[mi], base + sw_off(r, kk * 2 + (lane >> 4)));
            }
#pragma unroll
            for (int p = 0; p < 4; p++) {
                uint32_t bh[4];
                int r = warp_n + p * 16 + (lane & 7) + ((lane >> 4) << 3);
                ldsm4(bh, base + 8192 + sw_off(r, kk * 2 + ((lane >> 3) & 1)));
#pragma unroll
                for (int mi = 0; mi < 2; mi++) {
                    mma16816(acc[mi][p * 2], ah[mi], bh);
                    mma16816(acc[mi][p * 2 + 1], ah[mi], bh + 2);
                }
            }
        }
        __syncthreads();
    }
#pragma unroll
    for (int mi = 0; mi < 2; mi++) {
#pragma unroll
        for (int h = 0; h < 2; h++) {
            int t = t0 + warp_m + mi * 16 + (lane >> 2) + h * 8;
            int se = g_idx[t];
            float wv = g_w[t];
#pragma unroll
            for (int nt = 0; nt < 8; nt++) {
                int col = warp_n + nt * 8 + (lane & 3) * 2;
                float v0 = ((col >> 4) == se) ? wv * gelu_exact(acc[mi][nt][h * 2]) : 0.f;
                float v1 = (((col + 1) >> 4) == se) ? wv * gelu_exact(acc[mi][nt][h * 2 + 1]) : 0.f;
                __half2 p2 = __floats2half2_rn(v0, v1);
                *(uint32_t*)(g_hm + (size_t)t * ER + col) = *(uint32_t*)&p2;
            }
        }
    }
}

// ---------------- main kernel: BM=256, BN=128, 512 threads, 6 stages ----------------
// LoRA-B tail first (stashed fp16 in smem), then base GEMM, single fused write.
#define STG_SZ  24576
#define STG_W   16384
#define NSTAGE  6
#define STASH_OFF (NSTAGE * STG_SZ)         // 147456
#define SMEM_MAIN (STASH_OFF + 65536)       // 212992

__global__ __launch_bounds__(512, 1) void main_mma(
    const float* __restrict__ bb, float* __restrict__ out)
{
    extern __shared__ char sm[];
    uint32_t sb = smem_u32(sm);
    const int tid = threadIdx.x, wid = tid >> 5, lane = tid & 31;
    const int n0 = blockIdx.x * 128, t0 = blockIdx.y * 256;
    const int warp_m = (wid & 3) * 64, warp_n = (wid >> 2) * 32;

    float acc[4][4][4];
#pragma unroll
    for (int a = 0; a < 4; a++)
#pragma unroll
        for (int b = 0; b < 4; b++)
#pragma unroll
            for (int c = 0; c < 4; c++) acc[a][b][c] = 0.f;

    // ---------- LoRA-B tail first: acc = hm @ lBt^T (K=128) ----------
    {
#pragma unroll
        for (int c2 = 0; c2 < 4; c2++) {
            uint32_t st = sb + (uint32_t)c2 * STG_SZ;
            int k0 = c2 * 32;
#pragma unroll
            for (int i = 0; i < 2; i++) {
                int idx = tid + i * 512;
                int row = idx >> 2, ch = idx & 3;
                CP_ASYNC16(st + sw_off(row, ch), g_hm + (size_t)(t0 + row) * ER + k0 + ch * 8);
            }
            { int row = tid >> 2, ch = tid & 3;
              CP_ASYNC16(st + STG_W + sw_off(row, ch), g_lBt + (size_t)(n0 + row) * ER + k0 + ch * 8); }
            CP_COMMIT();
        }
        CP_WAIT(0);
        __syncthreads();
#pragma unroll
        for (int c2 = 0; c2 < 4; c2++) {
            uint32_t base = sb + (uint32_t)c2 * STG_SZ;
#pragma unroll
            for (int kk = 0; kk < 2; kk++) {
                uint32_t ah[4][4];
#pragma unroll
                for (int mi = 0; mi < 4; mi++) {
                    int r = warp_m + mi * 16 + (lane & 15);
                    ldsm4(ah[mi], base + sw_off(r, kk * 2 + (lane >> 4)));
                }
#pragma unroll
                for (int p = 0; p < 2; p++) {
                    uint32_t bh[4];
                    int r = warp_n + p * 16 + (lane & 7) + ((lane >> 4) << 3);
                    ldsm4(bh, base + STG_W + sw_off(r, kk * 2 + ((lane >> 3) & 1)));
#pragma unroll
                    for (int mi = 0; mi < 4; mi++) {
                        mma16816(acc[mi][p * 2],     ah[mi], bh);
                        mma16816(acc[mi][p * 2 + 1], ah[mi], bh + 2);
                    }
                }
            }
        }
        // stash to smem fp16 ([j][tid] layout, conflict-free) and zero acc
        uint32_t* stash = (uint32_t*)(sm + STASH_OFF);
#pragma unroll
        for (int mi = 0; mi < 4; mi++)
#pragma unroll
            for (int h = 0; h < 2; h++)
#pragma unroll
                for (int nj = 0; nj < 4; nj++) {
                    int j = (mi * 2 + h) * 4 + nj;
                    __half2 p2 = __floats2half2_rn(acc[mi][nj][h * 2], acc[mi][nj][h * 2 + 1]);
                    stash[j * 512 + tid] = *(uint32_t*)&p2;
                }
#pragma unroll
        for (int a = 0; a < 4; a++)
#pragma unroll
            for (int b = 0; b < 4; b++)
#pragma unroll
                for (int c = 0; c < 4; c++) acc[a][b][c] = 0.f;
        __syncthreads();   // all reads of tail stages done before reuse
    }

    // ---------- base GEMM: K = 2048, 64 chunks, 6-stage pipeline ----------
#define MN_ISSUE(s, k0) do {                                                  \
    uint32_t st = sb + (uint32_t)(s) * STG_SZ;                                \
    _Pragma("unroll")                                                         \
    for (int i = 0; i < 2; i++) {                                             \
        int idx = tid + i * 512;                                              \
        int row = idx >> 2, ch = idx & 3;                                     \
        CP_ASYNC16(st + sw_off(row, ch), g_xh + (size_t)(t0 + row) * DIM + (k0) + ch * 8); \
    }                                                                         \
    { int row = tid >> 2, ch = tid & 3;                                       \
      CP_ASYNC16(st + STG_W + sw_off(row, ch), g_wh + (size_t)(n0 + row) * DIM + (k0) + ch * 8); } \
    CP_COMMIT();                                                              \
} while (0)

    MN_ISSUE(0, 0);
    MN_ISSUE(1, 32);
    MN_ISSUE(2, 64);
    MN_ISSUE(3, 96);
    MN_ISSUE(4, 128);
    for (int c = 0; c < 64; c++) {
        if (c < 60)      { CP_WAIT(4); }
        else if (c == 60){ CP_WAIT(3); }
        else if (c == 61){ CP_WAIT(2); }
        else if (c == 62){ CP_WAIT(1); }
        else             { CP_WAIT(0); }
        __syncthreads();
        if (c + 5 < 64) MN_ISSUE((c + 5) % NSTAGE, (c + 5) * 32);
        uint32_t base = sb + (uint32_t)(c % NSTAGE) * STG_SZ;
#pragma unroll
        for (int kk = 0; kk < 2; kk++) {
            uint32_t ah[4][4];
#pragma unroll
            for (int mi = 0; mi < 4; mi++) {
                int r = warp_m + mi * 16 + (lane & 15);
                ldsm4(ah[mi], base + sw_off(r, kk * 2 + (lane >> 4)));
            }
#pragma unroll
            for (int p = 0; p < 2; p++) {
                uint32_t bh[4];
                int r = warp_n + p * 16 + (lane & 7) + ((lane >> 4) << 3);
                ldsm4(bh, base + STG_W + sw_off(r, kk * 2 + ((lane >> 3) & 1)));
#pragma unroll
                for (int mi = 0; mi < 4; mi++) {
                    mma16816(acc[mi][p * 2],     ah[mi], bh);
                    mma16816(acc[mi][p * 2 + 1], ah[mi], bh + 2);
                }
            }
        }
        __syncthreads();
    }

    // ---------- fused epilogue: out = gelu(base + bias) + stash ----------
    const uint32_t* stash = (const uint32_t*)(sm + STASH_OFF);
#pragma unroll
    for (int mi = 0; mi < 4; mi++) {
#pragma unroll
        for (int h = 0; h < 2; h++) {
            int t = t0 + warp_m + mi * 16 + (lane >> 2) + h * 8;
            float* orow = out + (size_t)t * DIM + n0 + warp_n;
#pragma unroll
            for (int nj = 0; nj < 4; nj++) {
                int col = nj * 8 + (lane & 3) * 2;
                int j = (mi * 2 + h) * 4 + nj;
                uint32_t lw = stash[j * 512 + tid];
                __half2 lv = *(__half2*)&lw;
                float b0 = __ldg(bb + n0 + warp_n + col);
                float b1 = __ldg(bb + n0 + warp_n + col + 1);
                float2 v;
                v.x = gelu_exact(acc[mi][nj][h * 2] + b0) + __low2float(lv);
                v.y = gelu_exact(acc[mi][nj][h * 2 + 1] + b1) + __high2float(lv);
                *(float2*)(orow + col) = v;
            }
        }
    }
}

// ---------------------------------------------------------------------------
extern "C" void kernel_launch(void* const* d_in, const int* in_sizes, int n_in,
                              void* d_out, int out_size)
{
    const float* x  = (const float*)d_in[0];
    const float* gw = (const float*)d_in[1];
    const float* gb = (const float*)d_in[2];
    const float* bw = (const float*)d_in[3];
    const float* bb = (const float*)d_in[4];
    const float* lA = (const float*)d_in[5];
    const float* lB = (const float*)d_in[6];

    float* out   = (float*)d_out;
    float* probs = out + (size_t)T_TOK * (size_t)DIM;

    cudaFuncSetAttribute(convx_router, cudaFuncAttributeMaxDynamicSharedMemorySize, NE * DIM * 4);
    cudaFuncSetAttribute(main_mma, cudaFuncAttributeMaxDynamicSharedMemorySize, SMEM_MAIN);
    cudaFuncSetAttribute(loraA_mma, cudaFuncAttributeMaxDynamicSharedMemorySize, 4 * LA_STAGE);

    convx_router<<<T_TOK / 8, 256, NE * DIM * 4>>>(x, gw, gb, probs);
    conv_w<<<DIM * DIM / 4 / 256, 256>>>(bw, DIM * DIM / 4);
    pack_lA_kernel<<<ER * DIM / 256, 256>>>(lA);
    pack_lB_kernel<<<DIM * ER / 256, 256>>>(lB);
    loraA_mma<<<T_TOK / 128, 256, 4 * LA_STAGE>>>();
    main_mma<<<dim3(DIM / 128, T_TOK / 256), 512, SMEM_MAIN>>>(bb, out);
}

// round 6
// speedup vs baseline: 1.0290x; 1.0290x over previous
#include <cuda_runtime.h>
#include <cuda_fp16.h>
#include <math.h>
#include <stdint.h>

#define T_TOK 8192
#define DIM   2048
#define NE    8
#define RK    16
#define ER    128

// ---------------- device scratch ----------------
__device__ int   g_idx[T_TOK];
__device__ float g_w[T_TOK];
__device__ __align__(256) __half g_xh[T_TOK * DIM];
__device__ __align__(256) __half g_wh[DIM * DIM];
__device__ __align__(256) __half g_lAt[ER * DIM];   // [n=e*16+r][k]
__device__ __align__(256) __half g_lBt[DIM * ER];   // [n][k2]
__device__ __align__(256) __half g_hm[T_TOK * ER];  // masked scaled h

__device__ __forceinline__ float gelu_exact(float v) {
    return 0.5f * v * (1.0f + erff(v * 0.7071067811865476f));
}
__device__ __forceinline__ uint32_t smem_u32(const void* p) {
    uint32_t a;
    asm("{ .reg .u64 t; cvta.to.shared.u64 t, %1; cvt.u32.u64 %0, t; }" : "=r"(a) : "l"(p));
    return a;
}
#define CP_ASYNC16(dst, src) asm volatile("cp.async.cg.shared.global [%0], [%1], 16;" :: "r"(dst), "l"(src))
#define CP_COMMIT()          asm volatile("cp.async.commit_group;" ::: "memory")
#define CP_WAIT(n)           asm volatile("cp.async.wait_group %0;" :: "n"(n) : "memory")

__device__ __forceinline__ void ldsm4(uint32_t* r, uint32_t addr) {
    asm volatile("ldmatrix.sync.aligned.m8n8.x4.shared.b16 {%0,%1,%2,%3}, [%4];"
        : "=r"(r[0]), "=r"(r[1]), "=r"(r[2]), "=r"(r[3]) : "r"(addr));
}
__device__ __forceinline__ void mma16816(float* d, const uint32_t* a, const uint32_t* b) {
    asm volatile("mma.sync.aligned.m16n8k16.row.col.f32.f16.f16.f32 "
        "{%0,%1,%2,%3}, {%4,%5,%6,%7}, {%8,%9}, {%0,%1,%2,%3};"
        : "+f"(d[0]), "+f"(d[1]), "+f"(d[2]), "+f"(d[3])
        : "r"(a[0]), "r"(a[1]), "r"(a[2]), "r"(a[3]), "r"(b[0]), "r"(b[1]));
}
// smem tile: rows x 64B (32 halves), swizzled
__device__ __forceinline__ uint32_t sw_off(int row, int chunk) {
    return (uint32_t)(row * 64 + ((chunk ^ ((row >> 1) & 3)) << 4));
}

// ---------------- fused x->fp16 convert + router (32 tokens/block) ----------------
__global__ __launch_bounds__(256) void convx_router(
    const float* __restrict__ x, const float* __restrict__ gw,
    const float* __restrict__ gb, float* __restrict__ probs)
{
    extern __shared__ char smc[];
    float (*sgw)[DIM] = (float(*)[DIM])smc;
    const int warp = threadIdx.x >> 5, lane = threadIdx.x & 31;

    for (int i = threadIdx.x; i < NE * (DIM / 4); i += 256)
        ((float4*)smc)[i] = ((const float4*)gw)[i];
    __syncthreads();

#pragma unroll 1
    for (int tt = 0; tt < 4; tt++) {
        const int t = blockIdx.x * 32 + warp * 4 + tt;
        const float* xr = x + (size_t)t * DIM;
        __half* xo = g_xh + (size_t)t * DIM;

        float acc[NE];
#pragma unroll
        for (int e = 0; e < NE; e++) acc[e] = 0.f;
#pragma unroll
        for (int i = 0; i < 16; i++) {
            int k = lane * 4 + i * 128;
            float4 v = *(const float4*)(xr + k);
            __half h[4] = {__float2half_rn(v.x), __float2half_rn(v.y),
                           __float2half_rn(v.z), __float2half_rn(v.w)};
            *(uint2*)(xo + k) = *(uint2*)h;
#pragma unroll
            for (int e = 0; e < NE; e++)
                acc[e] += v.x * sgw[e][k] + v.y * sgw[e][k + 1]
                        + v.z * sgw[e][k + 2] + v.w * sgw[e][k + 3];
        }
#pragma unroll
        for (int e = 0; e < NE; e++)
#pragma unroll
            for (int o = 16; o > 0; o >>= 1) acc[e] += __shfl_xor_sync(0xffffffffu, acc[e], o);
        if (lane == 0) {
            float m = -1e30f;
#pragma unroll
            for (int e = 0; e < NE; e++) { acc[e] += gb[e]; m = fmaxf(m, acc[e]); }
            float p[NE], s = 0.f;
#pragma unroll
            for (int e = 0; e < NE; e++) { p[e] = __expf(acc[e] - m); s += p[e]; }
            float inv = 1.f / s;
            int best = 0; float bp = -1.f;
#pragma unroll
            for (int e = 0; e < NE; e++) {
                p[e] *= inv;
                probs[t * NE + e] = p[e];
                if (p[e] > bp) { bp = p[e]; best = e; }
            }
            g_idx[t] = best; g_w[t] = bp;
        }
    }
}

// ---------------- prep kernels ----------------
__global__ __launch_bounds__(256) void conv_w(const float* __restrict__ src, int n4) {
    int i = blockIdx.x * 256 + threadIdx.x;
    if (i >= n4) return;
    float4 v = ((const float4*)src)[i];
    __half h[4] = {__float2half_rn(v.x), __float2half_rn(v.y),
                   __float2half_rn(v.z), __float2half_rn(v.w)};
    ((uint2*)g_wh)[i] = *(uint2*)h;
}
__global__ __launch_bounds__(256) void pack_lA_kernel(const float* __restrict__ lA) {
    int idx = blockIdx.x * 256 + threadIdx.x;
    int k = idx & (DIM - 1), n = idx >> 11;
    g_lAt[idx] = __float2half_rn(lA[(size_t)((n >> 4) * DIM + k) * RK + (n & 15)]);
}
__global__ __launch_bounds__(256) void pack_lB_kernel(const float* __restrict__ lB) {
    int idx = blockIdx.x * 256 + threadIdx.x;
    int k2 = idx & 127, n = idx >> 7;
    g_lBt[idx] = __float2half_rn(lB[(size_t)((k2 >> 4) * RK + (k2 & 15)) * DIM + n]);
}

// ---------------- LoRA-A: g_hm = mask(w * gelu(xh @ lAt^T)) ----------------
#define LA_STAGE 16384
__global__ __launch_bounds__(256, 2) void loraA_mma() {
    extern __shared__ char sm[];
    uint32_t sb = smem_u32(sm);
    const int tid = threadIdx.x, wid = tid >> 5, lane = tid & 31;
    const int t0 = blockIdx.x * 128;
    const int warp_m = (wid & 3) * 32, warp_n = (wid >> 2) * 64;
    const int lrow = tid >> 2, lc = tid & 3;

    float acc[2][8][4];
#pragma unroll
    for (int a = 0; a < 2; a++)
#pragma unroll
        for (int b = 0; b < 8; b++)
#pragma unroll
            for (int c = 0; c < 4; c++) acc[a][b][c] = 0.f;

#define LA_ISSUE(s, k0) do {                                                  \
    uint32_t st = sb + (uint32_t)(s) * LA_STAGE;                              \
    _Pragma("unroll")                                                         \
    for (int i = 0; i < 2; i++) {                                             \
        int row = lrow + i * 64;                                              \
        CP_ASYNC16(st + sw_off(row, lc), g_xh + (size_t)(t0 + row) * DIM + (k0) + lc * 8); \
        CP_ASYNC16(st + 8192 + sw_off(row, lc), g_lAt + (size_t)row * DIM + (k0) + lc * 8); \
    }                                                                         \
    CP_COMMIT();                                                              \
} while (0)

    LA_ISSUE(0, 0);
    LA_ISSUE(1, 32);
    LA_ISSUE(2, 64);
    for (int c = 0; c < 64; c++) {
        if (c < 62) { CP_WAIT(2); } else if (c == 62) { CP_WAIT(1); } else { CP_WAIT(0); }
        __syncthreads();
        if (c + 3 < 64) LA_ISSUE((c + 3) & 3, (c + 3) * 32);
        uint32_t base = sb + (uint32_t)(c & 3) * LA_STAGE;
#pragma unroll
        for (int kk = 0; kk < 2; kk++) {
            uint32_t ah[2][4];
#pragma unroll
            for (int mi = 0; mi < 2; mi++) {
                int r = warp_m + mi * 16 + (lane & 15);
                ldsm4(ah[mi], base + sw_off(r, kk * 2 + (lane >> 4)));
            }
#pragma unroll
            for (int p = 0; p < 4; p++) {
                uint32_t bh[4];
                int r = warp_n + p * 16 + (lane & 7) + ((lane >> 4) << 3);
                ldsm4(bh, base + 8192 + sw_off(r, kk * 2 + ((lane >> 3) & 1)));
#pragma unroll
                for (int mi = 0; mi < 2; mi++) {
                    mma16816(acc[mi][p * 2], ah[mi], bh);
                    mma16816(acc[mi][p * 2 + 1], ah[mi], bh + 2);
                }
            }
        }
        __syncthreads();
    }
#pragma unroll
    for (int mi = 0; mi < 2; mi++) {
#pragma unroll
        for (int h = 0; h < 2; h++) {
            int t = t0 + warp_m + mi * 16 + (lane >> 2) + h * 8;
            int se = g_idx[t];
            float wv = g_w[t];
#pragma unroll
            for (int nt = 0; nt < 8; nt++) {
                int col = warp_n + nt * 8 + (lane & 3) * 2;
                float v0 = ((col >> 4) == se) ? wv * gelu_exact(acc[mi][nt][h * 2]) : 0.f;
                float v1 = (((col + 1) >> 4) == se) ? wv * gelu_exact(acc[mi][nt][h * 2 + 1]) : 0.f;
                __half2 p2 = __floats2half2_rn(v0, v1);
                *(uint32_t*)(g_hm + (size_t)t * ER + col) = *(uint32_t*)&p2;
            }
        }
    }
}

// ---------------- main kernel: BM=128, BN=128, 256 threads, 2 CTAs/SM ----------------
// LoRA-B first into the 4 stages (one shot), stash fp16 in smem, base GEMM, fused write.
#define ST_WH   8192
#define STAGE_B 16384
#define STASH_OFF (4 * STAGE_B)            // 65536
#define SMEM_MAIN (STASH_OFF + 32768)      // 98304

__global__ __launch_bounds__(256, 2) void main_mma(
    const float* __restrict__ bb, float* __restrict__ out)
{
    extern __shared__ char sm[];
    uint32_t sb = smem_u32(sm);
    const int tid = threadIdx.x, wid = tid >> 5, lane = tid & 31;
    const int n0 = blockIdx.x * 128, t0 = blockIdx.y * 128;
    const int warp_m = (wid & 3) * 32, warp_n = (wid >> 2) * 64;
    const int lrow = tid >> 2, lc = tid & 3;

    float acc[2][8][4];
#pragma unroll
    for (int a = 0; a < 2; a++)
#pragma unroll
        for (int b = 0; b < 8; b++)
#pragma unroll
            for (int c = 0; c < 4; c++) acc[a][b][c] = 0.f;

    // ---------- LoRA-B first: acc = hm @ lBt^T (K=128), all 4 chunks at once ----------
    {
#pragma unroll
        for (int c2 = 0; c2 < 4; c2++) {
            uint32_t st = sb + (uint32_t)c2 * STAGE_B;
            int k0 = c2 * 32;
#pragma unroll
            for (int i = 0; i < 2; i++) {
                int row = lrow + i * 64;
                uint32_t so = sw_off(row, lc);
                CP_ASYNC16(st + so, g_hm + (size_t)(t0 + row) * ER + k0 + lc * 8);
                CP_ASYNC16(st + ST_WH + so, g_lBt + (size_t)(n0 + row) * ER + k0 + lc * 8);
            }
            CP_COMMIT();
        }
        CP_WAIT(0);
        __syncthreads();
#pragma unroll
        for (int c2 = 0; c2 < 4; c2++) {
            uint32_t base = sb + (uint32_t)c2 * STAGE_B;
#pragma unroll
            for (int kk = 0; kk < 2; kk++) {
                uint32_t ah[2][4];
#pragma unroll
                for (int mi = 0; mi < 2; mi++) {
                    int r = warp_m + mi * 16 + (lane & 15);
                    ldsm4(ah[mi], base + sw_off(r, kk * 2 + (lane >> 4)));
                }
#pragma unroll
                for (int p = 0; p < 4; p++) {
                    uint32_t bh[4];
                    int r = warp_n + p * 16 + (lane & 7) + ((lane >> 4) << 3);
                    ldsm4(bh, base + ST_WH + sw_off(r, kk * 2 + ((lane >> 3) & 1)));
#pragma unroll
                    for (int mi = 0; mi < 2; mi++) {
                        mma16816(acc[mi][p * 2], ah[mi], bh);
                        mma16816(acc[mi][p * 2 + 1], ah[mi], bh + 2);
                    }
                }
            }
        }
        // stash fp16 ([j][tid], conflict-free), zero acc
        uint32_t* stash = (uint32_t*)(sm + STASH_OFF);
#pragma unroll
        for (int mi = 0; mi < 2; mi++)
#pragma unroll
            for (int h = 0; h < 2; h++)
#pragma unroll
                for (int nt = 0; nt < 8; nt++) {
                    int j = (mi * 2 + h) * 8 + nt;
                    __half2 p2 = __floats2half2_rn(acc[mi][nt][h * 2], acc[mi][nt][h * 2 + 1]);
                    stash[j * 256 + tid] = *(uint32_t*)&p2;
                }
#pragma unroll
        for (int a = 0; a < 2; a++)
#pragma unroll
            for (int b = 0; b < 8; b++)
#pragma unroll
                for (int c = 0; c < 4; c++) acc[a][b][c] = 0.f;
        __syncthreads();
    }

    // ---------- base GEMM: K = 2048, 64 chunks, 4-stage pipeline ----------
#define MN_ISSUE(s, k0) do {                                                  \
    uint32_t st = sb + (uint32_t)(s) * STAGE_B;                               \
    _Pragma("unroll")                                                         \
    for (int i = 0; i < 2; i++) {                                             \
        int row = lrow + i * 64;                                              \
        uint32_t so = sw_off(row, lc);                                        \
        CP_ASYNC16(st + so, g_xh + (size_t)(t0 + row) * DIM + (k0) + lc * 8); \
        CP_ASYNC16(st + ST_WH + so, g_wh + (size_t)(n0 + row) * DIM + (k0) + lc * 8); \
    }                                                                         \
    CP_COMMIT();                                                              \
} while (0)

    MN_ISSUE(0, 0);
    MN_ISSUE(1, 32);
    MN_ISSUE(2, 64);
    for (int c = 0; c < 64; c++) {
        if (c < 62) { CP_WAIT(2); } else if (c == 62) { CP_WAIT(1); } else { CP_WAIT(0); }
        __syncthreads();
        if (c + 3 < 64) MN_ISSUE((c + 3) & 3, (c + 3) * 32);
        uint32_t base = sb + (uint32_t)(c & 3) * STAGE_B;
#pragma unroll
        for (int kk = 0; kk < 2; kk++) {
            uint32_t ah[2][4];
#pragma unroll
            for (int mi = 0; mi < 2; mi++) {
                int r = warp_m + mi * 16 + (lane & 15);
                ldsm4(ah[mi], base + sw_off(r, kk * 2 + (lane >> 4)));
            }
#pragma unroll
            for (int p = 0; p < 4; p++) {
                uint32_t bh[4];
                int r = warp_n + p * 16 + (lane & 7) + ((lane >> 4) << 3);
                ldsm4(bh, base + ST_WH + sw_off(r, kk * 2 + ((lane >> 3) & 1)));
#pragma unroll
                for (int mi = 0; mi < 2; mi++) {
                    mma16816(acc[mi][p * 2],     ah[mi], bh);
                    mma16816(acc[mi][p * 2 + 1], ah[mi], bh + 2);
                }
            }
        }
        __syncthreads();
    }

    // ---------- fused epilogue: out = gelu(base + bias) + stash ----------
    const uint32_t* stash = (const uint32_t*)(sm + STASH_OFF);
#pragma unroll
    for (int mi = 0; mi < 2; mi++) {
#pragma unroll
        for (int h = 0; h < 2; h++) {
            int t = t0 + warp_m + mi * 16 + (lane >> 2) + h * 8;
            float* orow = out + (size_t)t * DIM + n0 + warp_n;
#pragma unroll
            for (int nt = 0; nt < 8; nt++) {
                int col = nt * 8 + (lane & 3) * 2;
                int j = (mi * 2 + h) * 8 + nt;
                uint32_t lw = stash[j * 256 + tid];
                __half2 lv = *(__half2*)&lw;
                float b0 = __ldg(bb + n0 + warp_n + col);
                float b1 = __ldg(bb + n0 + warp_n + col + 1);
                float2 v;
                v.x = gelu_exact(acc[mi][nt][h * 2] + b0) + __low2float(lv);
                v.y = gelu_exact(acc[mi][nt][h * 2 + 1] + b1) + __high2float(lv);
                *(float2*)(orow + col) = v;
            }
        }
    }
}

// ---------------------------------------------------------------------------
extern "C" void kernel_launch(void* const* d_in, const int* in_sizes, int n_in,
                              void* d_out, int out_size)
{
    const float* x  = (const float*)d_in[0];
    const float* gw = (const float*)d_in[1];
    const float* gb = (const float*)d_in[2];
    const float* bw = (const float*)d_in[3];
    const float* bb = (const float*)d_in[4];
    const float* lA = (const float*)d_in[5];
    const float* lB = (const float*)d_in[6];

    float* out   = (float*)d_out;
    float* probs = out + (size_t)T_TOK * (size_t)DIM;

    cudaFuncSetAttribute(convx_router, cudaFuncAttributeMaxDynamicSharedMemorySize, NE * DIM * 4);
    cudaFuncSetAttribute(main_mma, cudaFuncAttributeMaxDynamicSharedMemorySize, SMEM_MAIN);
    cudaFuncSetAttribute(loraA_mma, cudaFuncAttributeMaxDynamicSharedMemorySize, 4 * LA_STAGE);

    convx_router<<<T_TOK / 32, 256, NE * DIM * 4>>>(x, gw, gb, probs);
    conv_w<<<DIM * DIM / 4 / 256, 256>>>(bw, DIM * DIM / 4);
    pack_lA_kernel<<<ER * DIM / 256, 256>>>(lA);
    pack_lB_kernel<<<DIM * ER / 256, 256>>>(lB);
    loraA_mma<<<T_TOK / 128, 256, 4 * LA_STAGE>>>();
    main_mma<<<dim3(DIM / 128, T_TOK / 128), 256, SMEM_MAIN>>>(bb, out);
}

// round 7
// speedup vs baseline: 1.0406x; 1.0113x over previous
#include <cuda_runtime.h>
#include <cuda_fp16.h>
#include <math.h>
#include <stdint.h>

#define T_TOK 8192
#define DIM   2048
#define NE    8
#define RK    16
#define ER    128

// ---------------- device scratch ----------------
__device__ int   g_idx[T_TOK];
__device__ float g_w[T_TOK];
__device__ __align__(256) __half g_xh[T_TOK * DIM];
__device__ __align__(256) __half g_wh[DIM * DIM];
__device__ __align__(256) __half g_lAt[ER * DIM];   // [n=e*16+r][k]
__device__ __align__(256) __half g_lBt[DIM * ER];   // [n][k2]
__device__ __align__(256) __half g_hm[T_TOK * ER];  // masked scaled h

__device__ __forceinline__ float gelu_exact(float v) {
    return 0.5f * v * (1.0f + erff(v * 0.7071067811865476f));
}
__device__ __forceinline__ uint32_t smem_u32(const void* p) {
    uint32_t a;
    asm("{ .reg .u64 t; cvta.to.shared.u64 t, %1; cvt.u32.u64 %0, t; }" : "=r"(a) : "l"(p));
    return a;
}
#define CP_ASYNC16(dst, src) asm volatile("cp.async.cg.shared.global [%0], [%1], 16;" :: "r"(dst), "l"(src))
#define CP_COMMIT()          asm volatile("cp.async.commit_group;" ::: "memory")
#define CP_WAIT(n)           asm volatile("cp.async.wait_group %0;" :: "n"(n) : "memory")

__device__ __forceinline__ void ldsm4(uint32_t* r, uint32_t addr) {
    asm volatile("ldmatrix.sync.aligned.m8n8.x4.shared.b16 {%0,%1,%2,%3}, [%4];"
        : "=r"(r[0]), "=r"(r[1]), "=r"(r[2]), "=r"(r[3]) : "r"(addr));
}
__device__ __forceinline__ void mma16816(float* d, const uint32_t* a, const uint32_t* b) {
    asm volatile("mma.sync.aligned.m16n8k16.row.col.f32.f16.f16.f32 "
        "{%0,%1,%2,%3}, {%4,%5,%6,%7}, {%8,%9}, {%0,%1,%2,%3};"
        : "+f"(d[0]), "+f"(d[1]), "+f"(d[2]), "+f"(d[3])
        : "r"(a[0]), "r"(a[1]), "r"(a[2]), "r"(a[3]), "r"(b[0]), "r"(b[1]));
}
// 64B-row swizzle (32 halves/row) — used by loraA
__device__ __forceinline__ uint32_t sw_off(int row, int chunk) {
    return (uint32_t)(row * 64 + ((chunk ^ ((row >> 1) & 3)) << 4));
}
// 128B-row SW128 swizzle (64 halves/row) — used by main
__device__ __forceinline__ uint32_t sw128(int row, int chunk) {
    uint32_t off = (uint32_t)(row * 128 + chunk * 16);
    return off ^ ((off >> 3) & 0x70);
}

// ---------------- fused x->fp16 convert + router (32 tokens/block) ----------------
__global__ __launch_bounds__(256) void convx_router(
    const float* __restrict__ x, const float* __restrict__ gw,
    const float* __restrict__ gb, float* __restrict__ probs)
{
    extern __shared__ char smc[];
    float (*sgw)[DIM] = (float(*)[DIM])smc;
    const int warp = threadIdx.x >> 5, lane = threadIdx.x & 31;

    for (int i = threadIdx.x; i < NE * (DIM / 4); i += 256)
        ((float4*)smc)[i] = ((const float4*)gw)[i];
    __syncthreads();

#pragma unroll 1
    for (int tt = 0; tt < 4; tt++) {
        const int t = blockIdx.x * 32 + warp * 4 + tt;
        const float* xr = x + (size_t)t * DIM;
        __half* xo = g_xh + (size_t)t * DIM;

        float acc[NE];
#pragma unroll
        for (int e = 0; e < NE; e++) acc[e] = 0.f;
#pragma unroll
        for (int i = 0; i < 16; i++) {
            int k = lane * 4 + i * 128;
            float4 v = *(const float4*)(xr + k);
            __half h[4] = {__float2half_rn(v.x), __float2half_rn(v.y),
                           __float2half_rn(v.z), __float2half_rn(v.w)};
            *(uint2*)(xo + k) = *(uint2*)h;
#pragma unroll
            for (int e = 0; e < NE; e++)
                acc[e] += v.x * sgw[e][k] + v.y * sgw[e][k + 1]
                        + v.z * sgw[e][k + 2] + v.w * sgw[e][k + 3];
        }
#pragma unroll
        for (int e = 0; e < NE; e++)
#pragma unroll
            for (int o = 16; o > 0; o >>= 1) acc[e] += __shfl_xor_sync(0xffffffffu, acc[e], o);
        if (lane == 0) {
            float m = -1e30f;
#pragma unroll
            for (int e = 0; e < NE; e++) { acc[e] += gb[e]; m = fmaxf(m, acc[e]); }
            float p[NE], s = 0.f;
#pragma unroll
            for (int e = 0; e < NE; e++) { p[e] = __expf(acc[e] - m); s += p[e]; }
            float inv = 1.f / s;
            int best = 0; float bp = -1.f;
#pragma unroll
            for (int e = 0; e < NE; e++) {
                p[e] *= inv;
                probs[t * NE + e] = p[e];
                if (p[e] > bp) { bp = p[e]; best = e; }
            }
            g_idx[t] = best; g_w[t] = bp;
        }
    }
}

// ---------------- prep kernels ----------------
__global__ __launch_bounds__(256) void conv_w(const float* __restrict__ src, int n4) {
    int i = blockIdx.x * 256 + threadIdx.x;
    if (i >= n4) return;
    float4 v = ((const float4*)src)[i];
    __half h[4] = {__float2half_rn(v.x), __float2half_rn(v.y),
                   __float2half_rn(v.z), __float2half_rn(v.w)};
    ((uint2*)g_wh)[i] = *(uint2*)h;
}
__global__ __launch_bounds__(256) void pack_lA_kernel(const float* __restrict__ lA) {
    int idx = blockIdx.x * 256 + threadIdx.x;
    int k = idx & (DIM - 1), n = idx >> 11;
    g_lAt[idx] = __float2half_rn(lA[(size_t)((n >> 4) * DIM + k) * RK + (n & 15)]);
}
__global__ __launch_bounds__(256) void pack_lB_kernel(const float* __restrict__ lB) {
    int idx = blockIdx.x * 256 + threadIdx.x;
    int k2 = idx & 127, n = idx >> 7;
    g_lBt[idx] = __float2half_rn(lB[(size_t)((k2 >> 4) * RK + (k2 & 15)) * DIM + n]);
}

// ---------------- LoRA-A: BM=64, grid=128 (full-chip wave) ----------------
// stage: x 64 rows (4KB) + lAt 128 rows (8KB) = 12KB; 4 stages.
#define LA_STAGE 12288
#define LA_WOFF  4096
__global__ __launch_bounds__(256, 2) void loraA_mma() {
    extern __shared__ char sm[];
    uint32_t sb = smem_u32(sm);
    const int tid = threadIdx.x, wid = tid >> 5, lane = tid & 31;
    const int t0 = blockIdx.x * 64;
    const int warp_m = (wid & 1) * 32, warp_n = (wid >> 1) * 32;

    float acc[2][4][4];
#pragma unroll
    for (int a = 0; a < 2; a++)
#pragma unroll
        for (int b = 0; b < 4; b++)
#pragma unroll
            for (int c = 0; c < 4; c++) acc[a][b][c] = 0.f;

#define LA_ISSUE(s, k0) do {                                                  \
    uint32_t st = sb + (uint32_t)(s) * LA_STAGE;                              \
    { int row = tid >> 2, ch = tid & 3;                                       \
      CP_ASYNC16(st + sw_off(row, ch), g_xh + (size_t)(t0 + row) * DIM + (k0) + ch * 8); } \
    _Pragma("unroll")                                                         \
    for (int i = 0; i < 2; i++) {                                             \
        int idx = tid + i * 256;                                              \
        int row = idx >> 2, ch = idx & 3;                                     \
        CP_ASYNC16(st + LA_WOFF + sw_off(row, ch), g_lAt + (size_t)row * DIM + (k0) + ch * 8); \
    }                                                                         \
    CP_COMMIT();                                                              \
} while (0)

    LA_ISSUE(0, 0);
    LA_ISSUE(1, 32);
    LA_ISSUE(2, 64);
    for (int c = 0; c < 64; c++) {
        if (c < 62) { CP_WAIT(2); } else if (c == 62) { CP_WAIT(1); } else { CP_WAIT(0); }
        __syncthreads();
        if (c + 3 < 64) LA_ISSUE((c + 3) & 3, (c + 3) * 32);
        uint32_t base = sb + (uint32_t)(c & 3) * LA_STAGE;
#pragma unroll
        for (int kk = 0; kk < 2; kk++) {
            uint32_t ah[2][4];
#pragma unroll
            for (int mi = 0; mi < 2; mi++) {
                int r = warp_m + mi * 16 + (lane & 15);
                ldsm4(ah[mi], base + sw_off(r, kk * 2 + (lane >> 4)));
            }
#pragma unroll
            for (int p = 0; p < 2; p++) {
                uint32_t bh[4];
                int r = warp_n + p * 16 + (lane & 7) + ((lane >> 4) << 3);
                ldsm4(bh, base + LA_WOFF + sw_off(r, kk * 2 + ((lane >> 3) & 1)));
#pragma unroll
                for (int mi = 0; mi < 2; mi++) {
                    mma16816(acc[mi][p * 2], ah[mi], bh);
                    mma16816(acc[mi][p * 2 + 1], ah[mi], bh + 2);
                }
            }
        }
        __syncthreads();
    }
#pragma unroll
    for (int mi = 0; mi < 2; mi++) {
#pragma unroll
        for (int h = 0; h < 2; h++) {
            int t = t0 + warp_m + mi * 16 + (lane >> 2) + h * 8;
            int se = g_idx[t];
            float wv = g_w[t];
#pragma unroll
            for (int nt = 0; nt < 4; nt++) {
                int col = warp_n + nt * 8 + (lane & 3) * 2;
                float v0 = ((col >> 4) == se) ? wv * gelu_exact(acc[mi][nt][h * 2]) : 0.f;
                float v1 = (((col + 1) >> 4) == se) ? wv * gelu_exact(acc[mi][nt][h * 2 + 1]) : 0.f;
                __half2 p2 = __floats2half2_rn(v0, v1);
                *(uint32_t*)(g_hm + (size_t)t * ER + col) = *(uint32_t*)&p2;
            }
        }
    }
}

// ---------------- main kernel: BM=128, BN=128, BK=64, 3 stages, 2 CTAs/SM ----------------
#define ST_WH   16384
#define STAGE_B 32768
#define NST     3
#define SMEM_MAIN (NST * STAGE_B)   // 98304

__global__ __launch_bounds__(256, 2) void main_mma(
    const float* __restrict__ bb, float* __restrict__ out)
{
    extern __shared__ char sm[];
    uint32_t sb = smem_u32(sm);
    const int tid = threadIdx.x, wid = tid >> 5, lane = tid & 31;
    const int n0 = blockIdx.x * 128, t0 = blockIdx.y * 128;
    const int warp_m = (wid & 3) * 32, warp_n = (wid >> 2) * 64;

    float acc[2][8][4];
#pragma unroll
    for (int a = 0; a < 2; a++)
#pragma unroll
        for (int b = 0; b < 8; b++)
#pragma unroll
            for (int c = 0; c < 4; c++) acc[a][b][c] = 0.f;

#define MN_ISSUE(s, k0) do {                                                  \
    uint32_t st = sb + (uint32_t)(s) * STAGE_B;                               \
    _Pragma("unroll")                                                         \
    for (int i = 0; i < 4; i++) {                                             \
        int idx = tid + i * 256;                                              \
        int row = idx >> 3, ch = idx & 7;                                     \
        uint32_t so = sw128(row, ch);                                         \
        CP_ASYNC16(st + so, g_xh + (size_t)(t0 + row) * DIM + (k0) + ch * 8); \
        CP_ASYNC16(st + ST_WH + so, g_wh + (size_t)(n0 + row) * DIM + (k0) + ch * 8); \
    }                                                                         \
    CP_COMMIT();                                                              \
} while (0)

    MN_ISSUE(0, 0);
    MN_ISSUE(1, 64);
    for (int c = 0; c < 32; c++) {
        if (c < 30) { CP_WAIT(1); } else { CP_WAIT(0); }
        __syncthreads();
        if (c + 2 < 32) MN_ISSUE((c + 2) % NST, (c + 2) * 64);
        uint32_t base = sb + (uint32_t)(c % NST) * STAGE_B;
#pragma unroll
        for (int kk = 0; kk < 4; kk++) {
            uint32_t ah[2][4];
#pragma unroll
            for (int mi = 0; mi < 2; mi++) {
                int r = warp_m + mi * 16 + (lane & 15);
                ldsm4(ah[mi], base + sw128(r, kk * 2 + (lane >> 4)));
            }
#pragma unroll
            for (int p = 0; p < 4; p++) {
                uint32_t bh[4];
                int r = warp_n + p * 16 + (lane & 7) + ((lane >> 4) << 3);
                ldsm4(bh, base + ST_WH + sw128(r, kk * 2 + ((lane >> 3) & 1)));
#pragma unroll
                for (int mi = 0; mi < 2; mi++) {
                    mma16816(acc[mi][p * 2],     ah[mi], bh);
                    mma16816(acc[mi][p * 2 + 1], ah[mi], bh + 2);
                }
            }
        }
        __syncthreads();
    }

    // ---- base epilogue: out = gelu(acc + bias) ----
#pragma unroll
    for (int mi = 0; mi < 2; mi++) {
#pragma unroll
        for (int h = 0; h < 2; h++) {
            int t = t0 + warp_m + mi * 16 + (lane >> 2) + h * 8;
            float* orow = out + (size_t)t * DIM + n0 + warp_n;
#pragma unroll
            for (int nt = 0; nt < 8; nt++) {
                int col = nt * 8 + (lane & 3) * 2;
                float b0 = __ldg(bb + n0 + warp_n + col);
                float b1 = __ldg(bb + n0 + warp_n + col + 1);
                float2 v;
                v.x = gelu_exact(acc[mi][nt][h * 2] + b0);
                v.y = gelu_exact(acc[mi][nt][h * 2 + 1] + b1);
                *(float2*)(orow + col) = v;
            }
        }
    }

    // ---- LoRA-B tail: acc = hm @ lBt^T (K=128 = 2 BK-chunks, one-shot load), out += ----
#pragma unroll
    for (int a = 0; a < 2; a++)
#pragma unroll
        for (int b = 0; b < 8; b++)
#pragma unroll
            for (int c = 0; c < 4; c++) acc[a][b][c] = 0.f;

    __syncthreads();
#pragma unroll
    for (int c2 = 0; c2 < 2; c2++) {
        uint32_t st = sb + (uint32_t)c2 * STAGE_B;
        int k0 = c2 * 64;
#pragma unroll
        for (int i = 0; i < 4; i++) {
            int idx = tid + i * 256;
            int row = idx >> 3, ch = idx & 7;
            uint32_t so = sw128(row, ch);
            CP_ASYNC16(st + so, g_hm + (size_t)(t0 + row) * ER + k0 + ch * 8);
            CP_ASYNC16(st + ST_WH + so, g_lBt + (size_t)(n0 + row) * ER + k0 + ch * 8);
        }
        CP_COMMIT();
    }
    CP_WAIT(0);
    __syncthreads();
#pragma unroll
    for (int c2 = 0; c2 < 2; c2++) {
        uint32_t base = sb + (uint32_t)c2 * STAGE_B;
#pragma unroll
        for (int kk = 0; kk < 4; kk++) {
            uint32_t ah[2][4];
#pragma unroll
            for (int mi = 0; mi < 2; mi++) {
                int r = warp_m + mi * 16 + (lane & 15);
                ldsm4(ah[mi], base + sw128(r, kk * 2 + (lane >> 4)));
            }
#pragma unroll
            for (int p = 0; p < 4; p++) {
                uint32_t bh[4];
                int r = warp_n + p * 16 + (lane & 7) + ((lane >> 4) << 3);
                ldsm4(bh, base + ST_WH + sw128(r, kk * 2 + ((lane >> 3) & 1)));
#pragma unroll
                for (int mi = 0; mi < 2; mi++) {
                    mma16816(acc[mi][p * 2], ah[mi], bh);
                    mma16816(acc[mi][p * 2 + 1], ah[mi], bh + 2);
                }
            }
        }
    }
#pragma unroll
    for (int mi = 0; mi < 2; mi++) {
#pragma unroll
        for (int h = 0; h < 2; h++) {
            int t = t0 + warp_m + mi * 16 + (lane >> 2) + h * 8;
            float* orow = out + (size_t)t * DIM + n0 + warp_n;
#pragma unroll
            for (int nt = 0; nt < 8; nt++) {
                int col = nt * 8 + (lane & 3) * 2;
                float2 v = *(float2*)(orow + col);
                v.x += acc[mi][nt][h * 2];
                v.y += acc[mi][nt][h * 2 + 1];
                *(float2*)(orow + col) = v;
            }
        }
    }
}

// ---------------------------------------------------------------------------
extern "C" void kernel_launch(void* const* d_in, const int* in_sizes, int n_in,
                              void* d_out, int out_size)
{
    const float* x  = (const float*)d_in[0];
    const float* gw = (const float*)d_in[1];
    const float* gb = (const float*)d_in[2];
    const float* bw = (const float*)d_in[3];
    const float* bb = (const float*)d_in[4];
    const float* lA = (const float*)d_in[5];
    const float* lB = (const float*)d_in[6];

    float* out   = (float*)d_out;
    float* probs = out + (size_t)T_TOK * (size_t)DIM;

    cudaFuncSetAttribute(convx_router, cudaFuncAttributeMaxDynamicSharedMemorySize, NE * DIM * 4);
    cudaFuncSetAttribute(main_mma, cudaFuncAttributeMaxDynamicSharedMemorySize, SMEM_MAIN);
    cudaFuncSetAttribute(loraA_mma, cudaFuncAttributeMaxDynamicSharedMemorySize, 4 * LA_STAGE);

    convx_router<<<T_TOK / 32, 256, NE * DIM * 4>>>(x, gw, gb, probs);
    conv_w<<<DIM * DIM / 4 / 256, 256>>>(bw, DIM * DIM / 4);
    pack_lA_kernel<<<ER * DIM / 256, 256>>>(lA);
    pack_lB_kernel<<<DIM * ER / 256, 256>>>(lB);
    loraA_mma<<<T_TOK / 64, 256, 4 * LA_STAGE>>>();
    main_mma<<<dim3(DIM / 128, T_TOK / 128), 256, SMEM_MAIN>>>(bb, out);
}

// round 8
// speedup vs baseline: 1.1089x; 1.0656x over previous
#include <cuda_runtime.h>
#include <cuda_fp16.h>
#include <math.h>
#include <stdint.h>

#define T_TOK 8192
#define DIM   2048
#define NE    8
#define RK    16
#define ER    128

// ---------------- device scratch ----------------
__device__ int   g_idx[T_TOK];
__device__ float g_w[T_TOK];
__device__ __align__(256) __half g_xh[T_TOK * DIM];
__device__ __align__(256) __half g_wh[DIM * DIM];
__device__ __align__(256) __half g_lAt[ER * DIM];   // [n=e*16+r][k]
__device__ __align__(256) __half g_lBt[DIM * ER];   // [n][k2]
__device__ __align__(256) __half g_hm[T_TOK * ER];  // masked scaled h

__device__ __forceinline__ float gelu_exact(float v) {
    return 0.5f * v * (1.0f + erff(v * 0.7071067811865476f));
}
__device__ __forceinline__ uint32_t smem_u32(const void* p) {
    uint32_t a;
    asm("{ .reg .u64 t; cvta.to.shared.u64 t, %1; cvt.u32.u64 %0, t; }" : "=r"(a) : "l"(p));
    return a;
}
#define CP_ASYNC16(dst, src) asm volatile("cp.async.cg.shared.global [%0], [%1], 16;" :: "r"(dst), "l"(src))
#define CP_COMMIT()          asm volatile("cp.async.commit_group;" ::: "memory")
#define CP_WAIT(n)           asm volatile("cp.async.wait_group %0;" :: "n"(n) : "memory")

__device__ __forceinline__ void ldsm4(uint32_t* r, uint32_t addr) {
    asm volatile("ldmatrix.sync.aligned.m8n8.x4.shared.b16 {%0,%1,%2,%3}, [%4];"
        : "=r"(r[0]), "=r"(r[1]), "=r"(r[2]), "=r"(r[3]) : "r"(addr));
}
__device__ __forceinline__ void mma16816(float* d, const uint32_t* a, const uint32_t* b) {
    asm volatile("mma.sync.aligned.m16n8k16.row.col.f32.f16.f16.f32 "
        "{%0,%1,%2,%3}, {%4,%5,%6,%7}, {%8,%9}, {%0,%1,%2,%3};"
        : "+f"(d[0]), "+f"(d[1]), "+f"(d[2]), "+f"(d[3])
        : "r"(a[0]), "r"(a[1]), "r"(a[2]), "r"(a[3]), "r"(b[0]), "r"(b[1]));
}
// smem tile: rows x 64B (32 halves), swizzled
__device__ __forceinline__ uint32_t sw_off(int row, int chunk) {
    return (uint32_t)(row * 64 + ((chunk ^ ((row >> 1) & 3)) << 4));
}

// ---------------- fused x->fp16 convert + router (round-4 exact) ----------------
__global__ __launch_bounds__(256) void convx_router(
    const float* __restrict__ x, const float* __restrict__ gw,
    const float* __restrict__ gb, float* __restrict__ probs)
{
    extern __shared__ char smc[];
    float (*sgw)[DIM] = (float(*)[DIM])smc;
    const int warp = threadIdx.x >> 5, lane = threadIdx.x & 31;
    const int t = blockIdx.x * 8 + warp;
    const float* xr = x + (size_t)t * DIM;
    __half* xo = g_xh + (size_t)t * DIM;

    for (int i = threadIdx.x; i < NE * (DIM / 4); i += 256)
        ((float4*)smc)[i] = ((const float4*)gw)[i];
    __syncthreads();

    float acc[NE];
#pragma unroll
    for (int e = 0; e < NE; e++) acc[e] = 0.f;
#pragma unroll
    for (int i = 0; i < 16; i++) {
        int k = lane * 4 + i * 128;
        float4 v = *(const float4*)(xr + k);
        __half h[4] = {__float2half_rn(v.x), __float2half_rn(v.y),
                       __float2half_rn(v.z), __float2half_rn(v.w)};
        *(uint2*)(xo + k) = *(uint2*)h;
#pragma unroll
        for (int e = 0; e < NE; e++)
            acc[e] += v.x * sgw[e][k] + v.y * sgw[e][k + 1]
                    + v.z * sgw[e][k + 2] + v.w * sgw[e][k + 3];
    }
#pragma unroll
    for (int e = 0; e < NE; e++)
#pragma unroll
        for (int o = 16; o > 0; o >>= 1) acc[e] += __shfl_xor_sync(0xffffffffu, acc[e], o);
    if (lane == 0) {
        float m = -1e30f;
#pragma unroll
        for (int e = 0; e < NE; e++) { acc[e] += gb[e]; m = fmaxf(m, acc[e]); }
        float p[NE], s = 0.f;
#pragma unroll
        for (int e = 0; e < NE; e++) { p[e] = __expf(acc[e] - m); s += p[e]; }
        float inv = 1.f / s;
        int best = 0; float bp = -1.f;
#pragma unroll
        for (int e = 0; e < NE; e++) {
            p[e] *= inv;
            probs[t * NE + e] = p[e];
            if (p[e] > bp) { bp = p[e]; best = e; }
        }
        g_idx[t] = best; g_w[t] = bp;
    }
}

// ---------------- fused prep: conv_w + pack_lA + pack_lB in one launch ----------------
// blocks [0, 4096): conv_w over DIM*DIM/4 float4 groups
// blocks [4096, 5120): pack_lA over ER*DIM elements
// blocks [5120, 6144): pack_lB over DIM*ER elements
__global__ __launch_bounds__(256) void prep_all(
    const float* __restrict__ bw, const float* __restrict__ lA,
    const float* __restrict__ lB)
{
    int b = blockIdx.x;
    if (b < 4096) {
        int i = b * 256 + threadIdx.x;
        float4 v = ((const float4*)bw)[i];
        __half h[4] = {__float2half_rn(v.x), __float2half_rn(v.y),
                       __float2half_rn(v.z), __float2half_rn(v.w)};
        ((uint2*)g_wh)[i] = *(uint2*)h;
    } else if (b < 5120) {
        int idx = (b - 4096) * 256 + threadIdx.x;
        int k = idx & (DIM - 1), n = idx >> 11;
        g_lAt[idx] = __float2half_rn(lA[(size_t)((n >> 4) * DIM + k) * RK + (n & 15)]);
    } else {
        int idx = (b - 5120) * 256 + threadIdx.x;
        int k2 = idx & 127, n = idx >> 7;
        g_lBt[idx] = __float2half_rn(lB[(size_t)((k2 >> 4) * RK + (k2 & 15)) * DIM + n]);
    }
}

// ---------------- LoRA-A (round-4 exact): BM=128, grid=64 ----------------
#define LA_STAGE 16384
__global__ __launch_bounds__(256, 2) void loraA_mma() {
    extern __shared__ char sm[];
    uint32_t sb = smem_u32(sm);
    const int tid = threadIdx.x, wid = tid >> 5, lane = tid & 31;
    const int t0 = blockIdx.x * 128;
    const int warp_m = (wid & 3) * 32, warp_n = (wid >> 2) * 64;
    const int lrow = tid >> 2, lc = tid & 3;

    float acc[2][8][4];
#pragma unroll
    for (int a = 0; a < 2; a++)
#pragma unroll
        for (int b = 0; b < 8; b++)
#pragma unroll
            for (int c = 0; c < 4; c++) acc[a][b][c] = 0.f;

#define LA_ISSUE(s, k0) do {                                                  \
    uint32_t st = sb + (uint32_t)(s) * LA_STAGE;                              \
    _Pragma("unroll")                                                         \
    for (int i = 0; i < 2; i++) {                                             \
        int row = lrow + i * 64;                                              \
        CP_ASYNC16(st + sw_off(row, lc), g_xh + (size_t)(t0 + row) * DIM + (k0) + lc * 8); \
        CP_ASYNC16(st + 8192 + sw_off(row, lc), g_lAt + (size_t)row * DIM + (k0) + lc * 8); \
    }                                                                         \
    CP_COMMIT();                                                              \
} while (0)

    LA_ISSUE(0, 0);
    LA_ISSUE(1, 32);
    LA_ISSUE(2, 64);
    for (int c = 0; c < 64; c++) {
        if (c < 62) { CP_WAIT(2); } else if (c == 62) { CP_WAIT(1); } else { CP_WAIT(0); }
        __syncthreads();
        if (c + 3 < 64) LA_ISSUE((c + 3) & 3, (c + 3) * 32);
        uint32_t base = sb + (uint32_t)(c & 3) * LA_STAGE;
#pragma unroll
        for (int kk = 0; kk < 2; kk++) {
            uint32_t ah[2][4];
#pragma unroll
            for (int mi = 0; mi < 2; mi++) {
                int r = warp_m + mi * 16 + (lane & 15);
                ldsm4(ah[mi], base + sw_off(r, kk * 2 + (lane >> 4)));
            }
#pragma unroll
            for (int p = 0; p < 4; p++) {
                uint32_t bh[4];
                int r = warp_n + p * 16 + (lane & 7) + ((lane >> 4) << 3);
                ldsm4(bh, base + 8192 + sw_off(r, kk * 2 + ((lane >> 3) & 1)));
#pragma unroll
                for (int mi = 0; mi < 2; mi++) {
                    mma16816(acc[mi][p * 2], ah[mi], bh);
                    mma16816(acc[mi][p * 2 + 1], ah[mi], bh + 2);
                }
            }
        }
        __syncthreads();
    }
#pragma unroll
    for (int mi = 0; mi < 2; mi++) {
#pragma unroll
        for (int h = 0; h < 2; h++) {
            int t = t0 + warp_m + mi * 16 + (lane >> 2) + h * 8;
            int se = g_idx[t];
            float wv = g_w[t];
#pragma unroll
            for (int nt = 0; nt < 8; nt++) {
                int col = warp_n + nt * 8 + (lane & 3) * 2;
                float v0 = ((col >> 4) == se) ? wv * gelu_exact(acc[mi][nt][h * 2]) : 0.f;
                float v1 = (((col + 1) >> 4) == se) ? wv * gelu_exact(acc[mi][nt][h * 2 + 1]) : 0.f;
                __half2 p2 = __floats2half2_rn(v0, v1);
                *(uint32_t*)(g_hm + (size_t)t * ER + col) = *(uint32_t*)&p2;
            }
        }
    }
}

// ---------------- main kernel (round-4 mainloop; tail loads hoisted) ----------------
#define ST_WH   8192
#define STAGE_B 16384

__global__ __launch_bounds__(256, 2) void main_mma(
    const float* __restrict__ bb, float* __restrict__ out)
{
    extern __shared__ char sm[];
    uint32_t sb = smem_u32(sm);
    const int tid = threadIdx.x, wid = tid >> 5, lane = tid & 31;
    const int n0 = blockIdx.x * 128, t0 = blockIdx.y * 128;
    const int warp_m = (wid & 3) * 32, warp_n = (wid >> 2) * 64;
    const int lrow = tid >> 2, lc = tid & 3;

    float acc[2][8][4];
#pragma unroll
    for (int a = 0; a < 2; a++)
#pragma unroll
        for (int b = 0; b < 8; b++)
#pragma unroll
            for (int c = 0; c < 4; c++) acc[a][b][c] = 0.f;

#define MN_ISSUE(s, k0) do {                                                  \
    uint32_t st = sb + (uint32_t)(s) * STAGE_B;                               \
    _Pragma("unroll")                                                         \
    for (int i = 0; i < 2; i++) {                                             \
        int row = lrow + i * 64;                                              \
        uint32_t so = sw_off(row, lc);                                        \
        CP_ASYNC16(st + so, g_xh + (size_t)(t0 + row) * DIM + (k0) + lc * 8); \
        CP_ASYNC16(st + ST_WH + so, g_wh + (size_t)(n0 + row) * DIM + (k0) + lc * 8); \
    }                                                                         \
    CP_COMMIT();                                                              \
} while (0)

    MN_ISSUE(0, 0);
    MN_ISSUE(1, 32);
    MN_ISSUE(2, 64);
    for (int c = 0; c < 64; c++) {
        if (c < 62) { CP_WAIT(2); } else if (c == 62) { CP_WAIT(1); } else { CP_WAIT(0); }
        __syncthreads();
        if (c + 3 < 64) MN_ISSUE((c + 3) & 3, (c + 3) * 32);
        uint32_t base = sb + (uint32_t)(c & 3) * STAGE_B;
#pragma unroll
        for (int kk = 0; kk < 2; kk++) {
            uint32_t ah[2][4];
#pragma unroll
            for (int mi = 0; mi < 2; mi++) {
                int r = warp_m + mi * 16 + (lane & 15);
                ldsm4(ah[mi], base + sw_off(r, kk * 2 + (lane >> 4)));
            }
#pragma unroll
            for (int p = 0; p < 4; p++) {
                uint32_t bh[4];
                int r = warp_n + p * 16 + (lane & 7) + ((lane >> 4) << 3);
                ldsm4(bh, base + ST_WH + sw_off(r, kk * 2 + ((lane >> 3) & 1)));
#pragma unroll
                for (int mi = 0; mi < 2; mi++) {
                    mma16816(acc[mi][p * 2],     ah[mi], bh);
                    mma16816(acc[mi][p * 2 + 1], ah[mi], bh + 2);
                }
            }
        }
        __syncthreads();
    }

    // ---- hoisted LoRA-B tail loads: all 4 chunks into the 4 stages, overlap epilogue ----
#pragma unroll
    for (int c2 = 0; c2 < 4; c2++) {
        uint32_t st = sb + (uint32_t)c2 * STAGE_B;
        int k0 = c2 * 32;
#pragma unroll
        for (int i = 0; i < 2; i++) {
            int row = lrow + i * 64;
            uint32_t so = sw_off(row, lc);
            CP_ASYNC16(st + so, g_hm + (size_t)(t0 + row) * ER + k0 + lc * 8);
            CP_ASYNC16(st + ST_WH + so, g_lBt + (size_t)(n0 + row) * ER + k0 + lc * 8);
        }
        CP_COMMIT();
    }

    // ---- base epilogue: out = gelu(acc + bias) (runs while tail loads fly) ----
#pragma unroll
    for (int mi = 0; mi < 2; mi++) {
#pragma unroll
        for (int h = 0; h < 2; h++) {
            int t = t0 + warp_m + mi * 16 + (lane >> 2) + h * 8;
            float* orow = out + (size_t)t * DIM + n0 + warp_n;
#pragma unroll
            for (int nt = 0; nt < 8; nt++) {
                int col = nt * 8 + (lane & 3) * 2;
                float b0 = __ldg(bb + n0 + warp_n + col);
                float b1 = __ldg(bb + n0 + warp_n + col + 1);
                float2 v;
                v.x = gelu_exact(acc[mi][nt][h * 2] + b0);
                v.y = gelu_exact(acc[mi][nt][h * 2 + 1] + b1);
                *(float2*)(orow + col) = v;
            }
        }
    }

    // ---- LoRA-B tail compute: acc = hm @ lBt^T (K=128), out += acc ----
#pragma unroll
    for (int a = 0; a < 2; a++)
#pragma unroll
        for (int b = 0; b < 8; b++)
#pragma unroll
            for (int c = 0; c < 4; c++) acc[a][b][c] = 0.f;

    CP_WAIT(0);
    __syncthreads();
#pragma unroll
    for (int c2 = 0; c2 < 4; c2++) {
        uint32_t base = sb + (uint32_t)c2 * STAGE_B;
#pragma unroll
        for (int kk = 0; kk < 2; kk++) {
            uint32_t ah[2][4];
#pragma unroll
            for (int mi = 0; mi < 2; mi++) {
                int r = warp_m + mi * 16 + (lane & 15);
                ldsm4(ah[mi], base + sw_off(r, kk * 2 + (lane >> 4)));
            }
#pragma unroll
            for (int p = 0; p < 4; p++) {
                uint32_t bh[4];
                int r = warp_n + p * 16 + (lane & 7) + ((lane >> 4) << 3);
                ldsm4(bh, base + ST_WH + sw_off(r, kk * 2 + ((lane >> 3) & 1)));
#pragma unroll
                for (int mi = 0; mi < 2; mi++) {
                    mma16816(acc[mi][p * 2], ah[mi], bh);
                    mma16816(acc[mi][p * 2 + 1], ah[mi], bh + 2);
                }
            }
        }
    }
#pragma unroll
    for (int mi = 0; mi < 2; mi++) {
#pragma unroll
        for (int h = 0; h < 2; h++) {
            int t = t0 + warp_m + mi * 16 + (lane >> 2) + h * 8;
            float* orow = out + (size_t)t * DIM + n0 + warp_n;
#pragma unroll
            for (int nt = 0; nt < 8; nt++) {
                int col = nt * 8 + (lane & 3) * 2;
                float2 v = *(float2*)(orow + col);
                v.x += acc[mi][nt][h * 2];
                v.y += acc[mi][nt][h * 2 + 1];
                *(float2*)(orow + col) = v;
            }
        }
    }
}

// ---------------------------------------------------------------------------
extern "C" void kernel_launch(void* const* d_in, const int* in_sizes, int n_in,
                              void* d_out, int out_size)
{
    const float* x  = (const float*)d_in[0];
    const float* gw = (const float*)d_in[1];
    const float* gb = (const float*)d_in[2];
    const float* bw = (const float*)d_in[3];
    const float* bb = (const float*)d_in[4];
    const float* lA = (const float*)d_in[5];
    const float* lB = (const float*)d_in[6];

    float* out   = (float*)d_out;
    float* probs = out + (size_t)T_TOK * (size_t)DIM;

    cudaFuncSetAttribute(convx_router, cudaFuncAttributeMaxDynamicSharedMemorySize, NE * DIM * 4);
    cudaFuncSetAttribute(main_mma, cudaFuncAttributeMaxDynamicSharedMemorySize, 4 * STAGE_B);
    cudaFuncSetAttribute(loraA_mma, cudaFuncAttributeMaxDynamicSharedMemorySize, 4 * LA_STAGE);

    convx_router<<<T_TOK / 8, 256, NE * DIM * 4>>>(x, gw, gb, probs);
    prep_all<<<6144, 256>>>(bw, lA, lB);
    loraA_mma<<<T_TOK / 128, 256, 4 * LA_STAGE>>>();
    main_mma<<<dim3(DIM / 128, T_TOK / 128), 256, 4 * STAGE_B>>>(bb, out);
}

// round 9
// speedup vs baseline: 1.2325x; 1.1114x over previous
#include <cuda_runtime.h>
#include <cuda_fp16.h>
#include <math.h>
#include <stdint.h>

#define T_TOK 8192
#define DIM   2048
#define NE    8
#define RK    16
#define ER    128

// ---------------- device scratch ----------------
__device__ int   g_idx[T_TOK];
__device__ float g_w[T_TOK];
__device__ __align__(256) __half g_xh[T_TOK * DIM];
__device__ __align__(256) __half g_wh[DIM * DIM];
__device__ __align__(256) __half g_lAt[ER * DIM];   // [n=e*16+r][k]
__device__ __align__(256) __half g_lBt[DIM * ER];   // [n][k2]
__device__ __align__(256) __half g_hm[T_TOK * ER];  // masked scaled h

__device__ __forceinline__ float gelu_exact(float v) {
    return 0.5f * v * (1.0f + erff(v * 0.7071067811865476f));
}
__device__ __forceinline__ uint32_t smem_u32(const void* p) {
    uint32_t a;
    asm("{ .reg .u64 t; cvta.to.shared.u64 t, %1; cvt.u32.u64 %0, t; }" : "=r"(a) : "l"(p));
    return a;
}
#define CP_ASYNC16(dst, src) asm volatile("cp.async.cg.shared.global [%0], [%1], 16;" :: "r"(dst), "l"(src))
#define CP_COMMIT()          asm volatile("cp.async.commit_group;" ::: "memory")
#define CP_WAIT(n)           asm volatile("cp.async.wait_group %0;" :: "n"(n) : "memory")

__device__ __forceinline__ void ldsm4(uint32_t* r, uint32_t addr) {
    asm volatile("ldmatrix.sync.aligned.m8n8.x4.shared.b16 {%0,%1,%2,%3}, [%4];"
        : "=r"(r[0]), "=r"(r[1]), "=r"(r[2]), "=r"(r[3]) : "r"(addr));
}
__device__ __forceinline__ void mma16816(float* d, const uint32_t* a, const uint32_t* b) {
    asm volatile("mma.sync.aligned.m16n8k16.row.col.f32.f16.f16.f32 "
        "{%0,%1,%2,%3}, {%4,%5,%6,%7}, {%8,%9}, {%0,%1,%2,%3};"
        : "+f"(d[0]), "+f"(d[1]), "+f"(d[2]), "+f"(d[3])
        : "r"(a[0]), "r"(a[1]), "r"(a[2]), "r"(a[3]), "r"(b[0]), "r"(b[1]));
}
// smem tile: rows x 64B (32 halves), swizzled
__device__ __forceinline__ uint32_t sw_off(int row, int chunk) {
    return (uint32_t)(row * 64 + ((chunk ^ ((row >> 1) & 3)) << 4));
}

// ---------------- fused x->fp16 convert + router ----------------
__global__ __launch_bounds__(256) void convx_router(
    const float* __restrict__ x, const float* __restrict__ gw,
    const float* __restrict__ gb, float* __restrict__ probs)
{
    extern __shared__ char smc[];
    float (*sgw)[DIM] = (float(*)[DIM])smc;
    const int warp = threadIdx.x >> 5, lane = threadIdx.x & 31;
    const int t = blockIdx.x * 8 + warp;
    const float* xr = x + (size_t)t * DIM;
    __half* xo = g_xh + (size_t)t * DIM;

    for (int i = threadIdx.x; i < NE * (DIM / 4); i += 256)
        ((float4*)smc)[i] = ((const float4*)gw)[i];
    __syncthreads();

    float acc[NE];
#pragma unroll
    for (int e = 0; e < NE; e++) acc[e] = 0.f;
#pragma unroll
    for (int i = 0; i < 16; i++) {
        int k = lane * 4 + i * 128;
        float4 v = *(const float4*)(xr + k);
        __half h[4] = {__float2half_rn(v.x), __float2half_rn(v.y),
                       __float2half_rn(v.z), __float2half_rn(v.w)};
        *(uint2*)(xo + k) = *(uint2*)h;
#pragma unroll
        for (int e = 0; e < NE; e++)
            acc[e] += v.x * sgw[e][k] + v.y * sgw[e][k + 1]
                    + v.z * sgw[e][k + 2] + v.w * sgw[e][k + 3];
    }
#pragma unroll
    for (int e = 0; e < NE; e++)
#pragma unroll
        for (int o = 16; o > 0; o >>= 1) acc[e] += __shfl_xor_sync(0xffffffffu, acc[e], o);
    if (lane == 0) {
        float m = -1e30f;
#pragma unroll
        for (int e = 0; e < NE; e++) { acc[e] += gb[e]; m = fmaxf(m, acc[e]); }
        float p[NE], s = 0.f;
#pragma unroll
        for (int e = 0; e < NE; e++) { p[e] = __expf(acc[e] - m); s += p[e]; }
        float inv = 1.f / s;
        int best = 0; float bp = -1.f;
#pragma unroll
        for (int e = 0; e < NE; e++) {
            p[e] *= inv;
            probs[t * NE + e] = p[e];
            if (p[e] > bp) { bp = p[e]; best = e; }
        }
        g_idx[t] = best; g_w[t] = bp;
    }
}

// ---------------- fused prep ----------------
__global__ __launch_bounds__(256) void prep_all(
    const float* __restrict__ bw, const float* __restrict__ lA,
    const float* __restrict__ lB)
{
    int b = blockIdx.x;
    if (b < 4096) {
        int i = b * 256 + threadIdx.x;
        float4 v = ((const float4*)bw)[i];
        __half h[4] = {__float2half_rn(v.x), __float2half_rn(v.y),
                       __float2half_rn(v.z), __float2half_rn(v.w)};
        ((uint2*)g_wh)[i] = *(uint2*)h;
    } else if (b < 5120) {
        int idx = (b - 4096) * 256 + threadIdx.x;
        int k = idx & (DIM - 1), n = idx >> 11;
        g_lAt[idx] = __float2half_rn(lA[(size_t)((n >> 4) * DIM + k) * RK + (n & 15)]);
    } else {
        int idx = (b - 5120) * 256 + threadIdx.x;
        int k2 = idx & 127, n = idx >> 7;
        g_lBt[idx] = __float2half_rn(lB[(size_t)((k2 >> 4) * RK + (k2 & 15)) * DIM + n]);
    }
}

// ---------------- LoRA-A: BM=64, grid=128 (full-chip wave) ----------------
#define LA_STAGE 12288
#define LA_WOFF  4096
__global__ __launch_bounds__(256, 2) void loraA_mma() {
    extern __shared__ char sm[];
    uint32_t sb = smem_u32(sm);
    const int tid = threadIdx.x, wid = tid >> 5, lane = tid & 31;
    const int t0 = blockIdx.x * 64;
    const int warp_m = (wid & 1) * 32, warp_n = (wid >> 1) * 32;

    float acc[2][4][4];
#pragma unroll
    for (int a = 0; a < 2; a++)
#pragma unroll
        for (int b = 0; b < 4; b++)
#pragma unroll
            for (int c = 0; c < 4; c++) acc[a][b][c] = 0.f;

#define LA_ISSUE(s, k0) do {                                                  \
    uint32_t st = sb + (uint32_t)(s) * LA_STAGE;                              \
    { int row = tid >> 2, ch = tid & 3;                                       \
      CP_ASYNC16(st + sw_off(row, ch), g_xh + (size_t)(t0 + row) * DIM + (k0) + ch * 8); } \
    _Pragma("unroll")                                                         \
    for (int i = 0; i < 2; i++) {                                             \
        int idx = tid + i * 256;                                              \
        int row = idx >> 2, ch = idx & 3;                                     \
        CP_ASYNC16(st + LA_WOFF + sw_off(row, ch), g_lAt + (size_t)row * DIM + (k0) + ch * 8); \
    }                                                                         \
    CP_COMMIT();                                                              \
} while (0)

    LA_ISSUE(0, 0);
    LA_ISSUE(1, 32);
    LA_ISSUE(2, 64);
    for (int c = 0; c < 64; c++) {
        if (c < 62) { CP_WAIT(2); } else if (c == 62) { CP_WAIT(1); } else { CP_WAIT(0); }
        __syncthreads();
        if (c + 3 < 64) LA_ISSUE((c + 3) & 3, (c + 3) * 32);
        uint32_t base = sb + (uint32_t)(c & 3) * LA_STAGE;
#pragma unroll
        for (int kk = 0; kk < 2; kk++) {
            uint32_t ah[2][4];
#pragma unroll
            for (int mi = 0; mi < 2; mi++) {
                int r = warp_m + mi * 16 + (lane & 15);
                ldsm4(ah[mi], base + sw_off(r, kk * 2 + (lane >> 4)));
            }
#pragma unroll
            for (int p = 0; p < 2; p++) {
                uint32_t bh[4];
                int r = warp_n + p * 16 + (lane & 7) + ((lane >> 4) << 3);
                ldsm4(bh, base + LA_WOFF + sw_off(r, kk * 2 + ((lane >> 3) & 1)));
#pragma unroll
                for (int mi = 0; mi < 2; mi++) {
                    mma16816(acc[mi][p * 2], ah[mi], bh);
                    mma16816(acc[mi][p * 2 + 1], ah[mi], bh + 2);
                }
            }
        }
        // trailing barrier removed: top-of-loop barrier orders reads before refill
    }
#pragma unroll
    for (int mi = 0; mi < 2; mi++) {
#pragma unroll
        for (int h = 0; h < 2; h++) {
            int t = t0 + warp_m + mi * 16 + (lane >> 2) + h * 8;
            int se = g_idx[t];
            float wv = g_w[t];
#pragma unroll
            for (int nt = 0; nt < 4; nt++) {
                int col = warp_n + nt * 8 + (lane & 3) * 2;
                float v0 = ((col >> 4) == se) ? wv * gelu_exact(acc[mi][nt][h * 2]) : 0.f;
                float v1 = (((col + 1) >> 4) == se) ? wv * gelu_exact(acc[mi][nt][h * 2 + 1]) : 0.f;
                __half2 p2 = __floats2half2_rn(v0, v1);
                *(uint32_t*)(g_hm + (size_t)t * ER + col) = *(uint32_t*)&p2;
            }
        }
    }
}

// ---------------- main kernel: BM=128, BN=128, BK=32, 5 stages, 2 CTAs/SM ----------------
#define ST_WH   8192
#define STAGE_B 16384
#define NSTAGE  5

__global__ __launch_bounds__(256, 2) void main_mma(
    const float* __restrict__ bb, float* __restrict__ out)
{
    extern __shared__ char sm[];
    uint32_t sb = smem_u32(sm);
    const int tid = threadIdx.x, wid = tid >> 5, lane = tid & 31;
    const int n0 = blockIdx.x * 128, t0 = blockIdx.y * 128;
    const int warp_m = (wid & 3) * 32, warp_n = (wid >> 2) * 64;
    const int lrow = tid >> 2, lc = tid & 3;

    // loop-invariant ldsm offsets (relative to stage base)
    uint32_t aoffs[2][2], boffs[2][4];
#pragma unroll
    for (int kk = 0; kk < 2; kk++) {
#pragma unroll
        for (int mi = 0; mi < 2; mi++)
            aoffs[kk][mi] = sw_off(warp_m + mi * 16 + (lane & 15), kk * 2 + (lane >> 4));
#pragma unroll
        for (int p = 0; p < 4; p++)
            boffs[kk][p] = ST_WH + sw_off(warp_n + p * 16 + (lane & 7) + ((lane >> 4) << 3),
                                          kk * 2 + ((lane >> 3) & 1));
    }

    float acc[2][8][4];
#pragma unroll
    for (int a = 0; a < 2; a++)
#pragma unroll
        for (int b = 0; b < 8; b++)
#pragma unroll
            for (int c = 0; c < 4; c++) acc[a][b][c] = 0.f;

#define MN_ISSUE(s, k0) do {                                                  \
    uint32_t st = sb + (uint32_t)(s) * STAGE_B;                               \
    _Pragma("unroll")                                                         \
    for (int i = 0; i < 2; i++) {                                             \
        int row = lrow + i * 64;                                              \
        uint32_t so = sw_off(row, lc);                                        \
        CP_ASYNC16(st + so, g_xh + (size_t)(t0 + row) * DIM + (k0) + lc * 8); \
        CP_ASYNC16(st + ST_WH + so, g_wh + (size_t)(n0 + row) * DIM + (k0) + lc * 8); \
    }                                                                         \
    CP_COMMIT();                                                              \
} while (0)

    MN_ISSUE(0, 0);
    MN_ISSUE(1, 32);
    MN_ISSUE(2, 64);
    MN_ISSUE(3, 96);
    int rs = 0, is = 4;
    for (int c = 0; c < 64; c++) {
        if (c < 61) { CP_WAIT(3); } else if (c == 61) { CP_WAIT(2); }
        else if (c == 62) { CP_WAIT(1); } else { CP_WAIT(0); }
        __syncthreads();
        if (c + 4 < 64) {
            MN_ISSUE(is, (c + 4) * 32);
            if (++is == NSTAGE) is = 0;
        }
        uint32_t base = sb + (uint32_t)rs * STAGE_B;
        if (++rs == NSTAGE) rs = 0;
#pragma unroll
        for (int kk = 0; kk < 2; kk++) {
            uint32_t ah[2][4];
            ldsm4(ah[0], base + aoffs[kk][0]);
            ldsm4(ah[1], base + aoffs[kk][1]);
#pragma unroll
            for (int p = 0; p < 4; p++) {
                uint32_t bh[4];
                ldsm4(bh, base + boffs[kk][p]);
#pragma unroll
                for (int mi = 0; mi < 2; mi++) {
                    mma16816(acc[mi][p * 2],     ah[mi], bh);
                    mma16816(acc[mi][p * 2 + 1], ah[mi], bh + 2);
                }
            }
        }
        // trailing barrier removed
    }

    // ---- hoisted LoRA-B tail loads into stages 0..3, overlap with epilogue ----
#pragma unroll
    for (int c2 = 0; c2 < 4; c2++) {
        uint32_t st = sb + (uint32_t)c2 * STAGE_B;
        int k0 = c2 * 32;
#pragma unroll
        for (int i = 0; i < 2; i++) {
            int row = lrow + i * 64;
            uint32_t so = sw_off(row, lc);
            CP_ASYNC16(st + so, g_hm + (size_t)(t0 + row) * ER + k0 + lc * 8);
            CP_ASYNC16(st + ST_WH + so, g_lBt + (size_t)(n0 + row) * ER + k0 + lc * 8);
        }
        CP_COMMIT();
    }

    // ---- base epilogue: out = gelu(acc + bias), bias hoisted ----
    float bias[8][2];
#pragma unroll
    for (int nt = 0; nt < 8; nt++) {
        int col = nt * 8 + (lane & 3) * 2;
        bias[nt][0] = __ldg(bb + n0 + warp_n + col);
        bias[nt][1] = __ldg(bb + n0 + warp_n + col + 1);
    }
#pragma unroll
    for (int mi = 0; mi < 2; mi++) {
#pragma unroll
        for (int h = 0; h < 2; h++) {
            int t = t0 + warp_m + mi * 16 + (lane >> 2) + h * 8;
            float* orow = out + (size_t)t * DIM + n0 + warp_n;
#pragma unroll
            for (int nt = 0; nt < 8; nt++) {
                int col = nt * 8 + (lane & 3) * 2;
                float2 v;
                v.x = gelu_exact(acc[mi][nt][h * 2] + bias[nt][0]);
                v.y = gelu_exact(acc[mi][nt][h * 2 + 1] + bias[nt][1]);
                *(float2*)(orow + col) = v;
            }
        }
    }

    // ---- LoRA-B tail compute: acc = hm @ lBt^T (K=128), out += acc ----
#pragma unroll
    for (int a = 0; a < 2; a++)
#pragma unroll
        for (int b = 0; b < 8; b++)
#pragma unroll
            for (int c = 0; c < 4; c++) acc[a][b][c] = 0.f;

    CP_WAIT(0);
    __syncthreads();
#pragma unroll
    for (int c2 = 0; c2 < 4; c2++) {
        uint32_t base = sb + (uint32_t)c2 * STAGE_B;
#pragma unroll
        for (int kk = 0; kk < 2; kk++) {
            uint32_t ah[2][4];
            ldsm4(ah[0], base + aoffs[kk][0]);
            ldsm4(ah[1], base + aoffs[kk][1]);
#pragma unroll
            for (int p = 0; p < 4; p++) {
                uint32_t bh[4];
                ldsm4(bh, base + boffs[kk][p]);
#pragma unroll
                for (int mi = 0; mi < 2; mi++) {
                    mma16816(acc[mi][p * 2], ah[mi], bh);
                    mma16816(acc[mi][p * 2 + 1], ah[mi], bh + 2);
                }
            }
        }
    }
#pragma unroll
    for (int mi = 0; mi < 2; mi++) {
#pragma unroll
        for (int h = 0; h < 2; h++) {
            int t = t0 + warp_m + mi * 16 + (lane >> 2) + h * 8;
            float* orow = out + (size_t)t * DIM + n0 + warp_n;
#pragma unroll
            for (int nt = 0; nt < 8; nt++) {
                int col = nt * 8 + (lane & 3) * 2;
                float2 v = *(float2*)(orow + col);
                v.x += acc[mi][nt][h * 2];
                v.y += acc[mi][nt][h * 2 + 1];
                *(float2*)(orow + col) = v;
            }
        }
    }
}

// ---------------------------------------------------------------------------
extern "C" void kernel_launch(void* const* d_in, const int* in_sizes, int n_in,
                              void* d_out, int out_size)
{
    const float* x  = (const float*)d_in[0];
    const float* gw = (const float*)d_in[1];
    const float* gb = (const float*)d_in[2];
    const float* bw = (const float*)d_in[3];
    const float* bb = (const float*)d_in[4];
    const float* lA = (const float*)d_in[5];
    const float* lB = (const float*)d_in[6];

    float* out   = (float*)d_out;
    float* probs = out + (size_t)T_TOK * (size_t)DIM;

    cudaFuncSetAttribute(convx_router, cudaFuncAttributeMaxDynamicSharedMemorySize, NE * DIM * 4);
    cudaFuncSetAttribute(main_mma, cudaFuncAttributeMaxDynamicSharedMemorySize, NSTAGE * STAGE_B);
    cudaFuncSetAttribute(loraA_mma, cudaFuncAttributeMaxDynamicSharedMemorySize, 4 * LA_STAGE);

    convx_router<<<T_TOK / 8, 256, NE * DIM * 4>>>(x, gw, gb, probs);
    prep_all<<<6144, 256>>>(bw, lA, lB);
    loraA_mma<<<T_TOK / 64, 256, 4 * LA_STAGE>>>();
    main_mma<<<dim3(DIM / 128, T_TOK / 128), 256, NSTAGE * STAGE_B>>>(bb, out);
}